// round 9
// baseline (speedup 1.0000x reference)
#include <cuda_runtime.h>
#include <cuda_fp16.h>
#include <cstdint>

// ---------------- problem constants ----------------
#define TOKENS 8192
#define DIN    4096
#define DOUT   4096

// ---------------- GEMM tiling ----------------
#define BM 128                 // CTA tile M
#define BN 64                  // CTA tile N
#define BK 64                  // fp16 elements per K stage (128B per row)
#define STAGES 3
#define NKT (DIN / BK)         // 64 K iterations
#define NTHREADS 256           // 8 warps: 2 (m) x 4 (n), warp tile 64x16

// SMEM row stride: 128B data + 16B pad = 144B -> ldmatrix phases conflict-free.
#define STRIDE 144
#define A_OFF 0
#define A_BYTES (BM * STRIDE)            // 18432
#define B_OFF A_BYTES
#define B_BYTES (BN * STRIDE)            // 9216
#define STAGE_BYTES (A_BYTES + B_BYTES)  // 27648
#define SMEM_BYTES (STAGES * STAGE_BYTES)// 82944 -> 2 CTAs/SM

// ---------------- device scratch ----------------
__device__ __half g_w[(size_t)DOUT   * DIN];   // 32 MB; codes 0..126 EXACT in fp16
__device__ __half g_x[(size_t)TOKENS * DIN];   // 64 MB; rel err <= 2^-11/element

// ---------------- PTX helpers ----------------
__device__ __forceinline__ uint32_t smem_u32(const void* p) {
    return (uint32_t)__cvta_generic_to_shared(p);
}
__device__ __forceinline__ void cp16(uint32_t s, const void* g) {
    asm volatile("cp.async.cg.shared.global [%0], [%1], 16;" :: "r"(s), "l"(g));
}
__device__ __forceinline__ void cp_commit() {
    asm volatile("cp.async.commit_group;" ::: "memory");
}
template <int N>
__device__ __forceinline__ void cp_wait() {
    asm volatile("cp.async.wait_group %0;" :: "n"(N) : "memory");
}
__device__ __forceinline__ void ldsm4(uint32_t* r, uint32_t addr) {
    asm volatile("ldmatrix.sync.aligned.m8n8.x4.shared.b16 {%0,%1,%2,%3}, [%4];"
                 : "=r"(r[0]), "=r"(r[1]), "=r"(r[2]), "=r"(r[3]) : "r"(addr));
}
__device__ __forceinline__ void mma16816(float* d, const uint32_t* a, const uint32_t* b) {
    asm volatile(
        "mma.sync.aligned.m16n8k16.row.col.f32.f16.f16.f32 "
        "{%0,%1,%2,%3}, {%4,%5,%6,%7}, {%8,%9}, {%0,%1,%2,%3};"
        : "+f"(d[0]), "+f"(d[1]), "+f"(d[2]), "+f"(d[3])
        : "r"(a[0]), "r"(a[1]), "r"(a[2]), "r"(a[3]), "r"(b[0]), "r"(b[1]));
}
// streaming 8B store (converted planes are consumed from L2/DRAM later; evict-first)
__device__ __forceinline__ void st_cs8(void* p, uint2 v) {
    asm volatile("st.global.cs.v2.u32 [%0], {%1, %2};" :: "l"(p), "r"(v.x), "r"(v.y));
}

// ---------------- fused conversion kernel ----------------
#define XN4 (TOKENS * DIN / 4)
#define WN4 (DOUT * DIN / 4)

__global__ void convert_all_kernel(const float4* __restrict__ x,
                                   const float4* __restrict__ w) {
    int i = blockIdx.x * blockDim.x + threadIdx.x;
    if (i < XN4) {
        float4 v = x[i];
        __half2 p0 = __floats2half2_rn(v.x, v.y);
        __half2 p1 = __floats2half2_rn(v.z, v.w);
        uint2 pk;
        pk.x = *reinterpret_cast<uint32_t*>(&p0);
        pk.y = *reinterpret_cast<uint32_t*>(&p1);
        st_cs8(reinterpret_cast<uint2*>(g_x) + i, pk);
    } else {
        int j = i - XN4;
        float4 v = w[j];
        __half2 p0 = __floats2half2_rn(v.x, v.y);   // exact: integer codes 0..126
        __half2 p1 = __floats2half2_rn(v.z, v.w);
        uint2 pk;
        pk.x = *reinterpret_cast<uint32_t*>(&p0);
        pk.y = *reinterpret_cast<uint32_t*>(&p1);
        st_cs8(reinterpret_cast<uint2*>(g_w) + j, pk);
    }
}

// ---------------- main GEMM ----------------
__global__ void __launch_bounds__(NTHREADS, 2)
gemm_kernel(const float* __restrict__ bias, const float* __restrict__ scale,
            float* __restrict__ out) {
    extern __shared__ char dsm[];
    const uint32_t base = smem_u32(dsm);

    const int tid  = threadIdx.x;
    const int lane = tid & 31;
    const int wrp  = tid >> 5;                 // 8 warps: 2 (m) x 4 (n)
    const int wm   = (wrp >> 2) * 64;          // warp m offset (0/64)
    const int wn   = (wrp & 3) * 16;           // warp n offset (0/16/32/48)
    const int gn0  = blockIdx.x * BN;
    const int gm0  = blockIdx.y * BM;

    // ---- per-thread cp.async state (advance src by 128B per stage) ----
    const int lrowc = tid >> 3;
    const int lseg  = tid & 7;
    const char* asrc = (const char*)(g_x + (size_t)(gm0 + lrowc) * DIN + lseg * 8);
    const char* bsrc = (const char*)(g_w + (size_t)(gn0 + lrowc) * DIN + lseg * 8);
    const uint32_t adst = base + A_OFF + lrowc * STRIDE + lseg * 16;
    const uint32_t bdst = base + B_OFF + lrowc * STRIDE + lseg * 16;

    #define LOAD_STAGE(slot)                                                        \
        do {                                                                        \
            const uint32_t so = (slot) * STAGE_BYTES;                               \
            _Pragma("unroll")                                                       \
            for (int t = 0; t < 4; t++)                                             \
                cp16(adst + so + t * (32 * STRIDE),                                 \
                     asrc + (size_t)t * (32 * DIN * 2));                            \
            _Pragma("unroll")                                                       \
            for (int t = 0; t < 2; t++)                                             \
                cp16(bdst + so + t * (32 * STRIDE),                                 \
                     bsrc + (size_t)t * (32 * DIN * 2));                            \
            cp_commit();                                                            \
        } while (0)

    const int lrow = lane & 15;
    const int lcol = (lane >> 4) * 16;

    float acc[4][2][4];
#pragma unroll
    for (int mi = 0; mi < 4; mi++)
#pragma unroll
        for (int ni = 0; ni < 2; ni++)
#pragma unroll
            for (int c = 0; c < 4; c++) acc[mi][ni][c] = 0.0f;

    // prologue: 2 stages in flight
    LOAD_STAGE(0);
    asrc += 128; bsrc += 128;
    LOAD_STAGE(1);
    asrc += 128; bsrc += 128;

    int slot = 0;                         // slot of stage kt
    int nslot = 2;                        // slot to fill with stage kt+2
    for (int kt = 0; kt < NKT; kt++) {
        // Groups committed: stages 0..kt+1. wait<1> retires stage kt while the
        // newest (kt+1, issued one full compute-block ago) may still fly ->
        // prefetch distance 2 compute-blocks, L2/DRAM latency fully covered.
        if (kt < NKT - 1) cp_wait<1>(); else cp_wait<0>();
        // Barrier also proves all warps finished reading slot `nslot`
        // (last read as stage kt-1) before we overwrite it below.
        __syncthreads();

        if (kt + 2 < NKT) {
            LOAD_STAGE(nslot);
            asrc += 128; bsrc += 128;
        } else {
            cp_commit();                  // keep group-count invariant uniform
        }

        const uint32_t st = base + slot * STAGE_BYTES;
        const uint32_t a_base = st + A_OFF + (wm + lrow) * STRIDE + lcol;
        const uint32_t b_base = st + B_OFF + (wn + lrow) * STRIDE + lcol;

#pragma unroll
        for (int ks = 0; ks < 4; ks++) {            // four k16 sub-steps
            uint32_t a[4][4];
#pragma unroll
            for (int mi = 0; mi < 4; mi++)
                ldsm4(a[mi], a_base + mi * 16 * STRIDE + ks * 32);

            uint32_t t4[4];                          // n16 x k16 -> two n8 frags
            ldsm4(t4, b_base + ks * 32);
            uint32_t b0[2] = {t4[0], t4[2]};
            uint32_t b1[2] = {t4[1], t4[3]};

#pragma unroll
            for (int mi = 0; mi < 4; mi++) {
                mma16816(acc[mi][0], a[mi], b0);
                mma16816(acc[mi][1], a[mi], b1);
            }
        }

        slot  = (slot  == STAGES - 1) ? 0 : slot + 1;
        nslot = (nslot == STAGES - 1) ? 0 : nslot + 1;
    }

    // ---------------- epilogue: y = acc * scale + bias ----------------
    const float sc = __ldg(scale);
    const int r0 = lane >> 2;
    const int c0 = 2 * (lane & 3);

#pragma unroll
    for (int ni = 0; ni < 2; ni++) {
        const int col = gn0 + wn + ni * 8 + c0;
        const float2 bv = *reinterpret_cast<const float2*>(bias + col);
#pragma unroll
        for (int mi = 0; mi < 4; mi++) {
            const int row = gm0 + wm + mi * 16 + r0;
            float2 o0, o1;
            o0.x = acc[mi][ni][0] * sc + bv.x;
            o0.y = acc[mi][ni][1] * sc + bv.y;
            o1.x = acc[mi][ni][2] * sc + bv.x;
            o1.y = acc[mi][ni][3] * sc + bv.y;
            *reinterpret_cast<float2*>(out + (size_t)row * DOUT + col)       = o0;
            *reinterpret_cast<float2*>(out + (size_t)(row + 8) * DOUT + col) = o1;
        }
    }
}

// ---------------- launch ----------------
extern "C" void kernel_launch(void* const* d_in, const int* in_sizes, int n_in,
                              void* d_out, int out_size) {
    const float* x     = (const float*)d_in[0];
    const float* w     = (const float*)d_in[1];
    const float* bias  = (const float*)d_in[2];
    const float* scale = (const float*)d_in[3];
    float* out = (float*)d_out;

    convert_all_kernel<<<(XN4 + WN4) / 256, 256>>>((const float4*)x, (const float4*)w);

    cudaFuncSetAttribute(gemm_kernel, cudaFuncAttributeMaxDynamicSharedMemorySize, SMEM_BYTES);
    dim3 grid(DOUT / BN, TOKENS / BM);   // (64, 64)
    gemm_kernel<<<grid, NTHREADS, SMEM_BYTES>>>(bias, scale, out);
}

// round 10
// speedup vs baseline: 1.1044x; 1.1044x over previous
#include <cuda_runtime.h>
#include <cuda_fp16.h>
#include <cstdint>

// ---------------- problem constants ----------------
#define TOKENS 8192
#define DIN    4096
#define DOUT   4096

// ---------------- GEMM tiling ----------------
#define BM 128                 // CTA tile M
#define BN 64                  // CTA tile N
#define BK 64                  // fp16 elements per K stage (128B per row)
#define NKT (DIN / BK)         // 64 K iterations
#define NTHREADS 256           // 8 warps: 2 (m) x 4 (n), warp tile 64x16

// SMEM row stride: 128B data + 16B pad = 144B -> ldmatrix phases conflict-free.
#define STRIDE 144
#define A_OFF 0
#define A_BYTES (BM * STRIDE)            // 18432
#define B_OFF A_BYTES
#define B_BYTES (BN * STRIDE)            // 9216
#define STAGE_BYTES (A_BYTES + B_BYTES)  // 27648
#define SMEM_BYTES (2 * STAGE_BYTES)     // 55296 -> 3 CTAs/SM (166KB < 228KB)

// ---------------- device scratch ----------------
__device__ __half g_w[(size_t)DOUT   * DIN];   // 32 MB; codes 0..126 EXACT in fp16
__device__ __half g_x[(size_t)TOKENS * DIN];   // 64 MB; rel err <= 2^-11/element

// ---------------- PTX helpers ----------------
__device__ __forceinline__ uint32_t smem_u32(const void* p) {
    return (uint32_t)__cvta_generic_to_shared(p);
}
__device__ __forceinline__ void cp16(uint32_t s, const void* g) {
    asm volatile("cp.async.cg.shared.global [%0], [%1], 16;" :: "r"(s), "l"(g));
}
__device__ __forceinline__ void cp_commit() {
    asm volatile("cp.async.commit_group;" ::: "memory");
}
template <int N>
__device__ __forceinline__ void cp_wait() {
    asm volatile("cp.async.wait_group %0;" :: "n"(N) : "memory");
}
__device__ __forceinline__ void ldsm4(uint32_t* r, uint32_t addr) {
    asm volatile("ldmatrix.sync.aligned.m8n8.x4.shared.b16 {%0,%1,%2,%3}, [%4];"
                 : "=r"(r[0]), "=r"(r[1]), "=r"(r[2]), "=r"(r[3]) : "r"(addr));
}
__device__ __forceinline__ void mma16816(float* d, const uint32_t* a, const uint32_t* b) {
    asm volatile(
        "mma.sync.aligned.m16n8k16.row.col.f32.f16.f16.f32 "
        "{%0,%1,%2,%3}, {%4,%5,%6,%7}, {%8,%9}, {%0,%1,%2,%3};"
        : "+f"(d[0]), "+f"(d[1]), "+f"(d[2]), "+f"(d[3])
        : "r"(a[0]), "r"(a[1]), "r"(a[2]), "r"(a[3]), "r"(b[0]), "r"(b[1]));
}
// streaming loads/stores for the one-shot convert pass (evict-first in L2)
__device__ __forceinline__ float4 ld_cs16(const float4* p) {
    float4 v;
    asm volatile("ld.global.cs.v4.f32 {%0,%1,%2,%3}, [%4];"
                 : "=f"(v.x), "=f"(v.y), "=f"(v.z), "=f"(v.w) : "l"(p));
    return v;
}
__device__ __forceinline__ void st_cs8(void* p, uint2 v) {
    asm volatile("st.global.cs.v2.u32 [%0], {%1, %2};" :: "l"(p), "r"(v.x), "r"(v.y));
}

// ---------------- fused conversion kernel ----------------
#define XN4 (TOKENS * DIN / 4)
#define WN4 (DOUT * DIN / 4)

__global__ void convert_all_kernel(const float4* __restrict__ x,
                                   const float4* __restrict__ w) {
    int i = blockIdx.x * blockDim.x + threadIdx.x;
    if (i < XN4) {
        float4 v = ld_cs16(x + i);
        __half2 p0 = __floats2half2_rn(v.x, v.y);
        __half2 p1 = __floats2half2_rn(v.z, v.w);
        uint2 pk;
        pk.x = *reinterpret_cast<uint32_t*>(&p0);
        pk.y = *reinterpret_cast<uint32_t*>(&p1);
        st_cs8(reinterpret_cast<uint2*>(g_x) + i, pk);
    } else {
        int j = i - XN4;
        float4 v = ld_cs16(w + j);
        __half2 p0 = __floats2half2_rn(v.x, v.y);   // exact: integer codes 0..126
        __half2 p1 = __floats2half2_rn(v.z, v.w);
        uint2 pk;
        pk.x = *reinterpret_cast<uint32_t*>(&p0);
        pk.y = *reinterpret_cast<uint32_t*>(&p1);
        st_cs8(reinterpret_cast<uint2*>(g_w) + j, pk);
    }
}

// ---------------- main GEMM (round-8 optimum: 2-stage, 3 CTAs/SM) ----------------
__global__ void __launch_bounds__(NTHREADS, 3)
gemm_kernel(const float* __restrict__ bias, const float* __restrict__ scale,
            float* __restrict__ out) {
    extern __shared__ char dsm[];
    const uint32_t base = smem_u32(dsm);

    const int tid  = threadIdx.x;
    const int lane = tid & 31;
    const int wrp  = tid >> 5;                 // 8 warps: 2 (m) x 4 (n)
    const int wm   = (wrp >> 2) * 64;          // warp m offset (0/64)
    const int wn   = (wrp & 3) * 16;           // warp n offset (0/16/32/48)
    const int gn0  = blockIdx.x * BN;
    const int gm0  = blockIdx.y * BM;

    // ---- per-thread cp.async state (advance src by 128B per stage) ----
    const int lrowc = tid >> 3;
    const int lseg  = tid & 7;
    const char* asrc = (const char*)(g_x + (size_t)(gm0 + lrowc) * DIN + lseg * 8);
    const char* bsrc = (const char*)(g_w + (size_t)(gn0 + lrowc) * DIN + lseg * 8);
    const uint32_t adst = base + A_OFF + lrowc * STRIDE + lseg * 16;
    const uint32_t bdst = base + B_OFF + lrowc * STRIDE + lseg * 16;

    #define LOAD_STAGE(slot)                                                        \
        do {                                                                        \
            const uint32_t so = (slot) * STAGE_BYTES;                               \
            _Pragma("unroll")                                                       \
            for (int t = 0; t < 4; t++)                                             \
                cp16(adst + so + t * (32 * STRIDE),                                 \
                     asrc + (size_t)t * (32 * DIN * 2));                            \
            _Pragma("unroll")                                                       \
            for (int t = 0; t < 2; t++)                                             \
                cp16(bdst + so + t * (32 * STRIDE),                                 \
                     bsrc + (size_t)t * (32 * DIN * 2));                            \
            cp_commit();                                                            \
        } while (0)

    const int lrow = lane & 15;
    const int lcol = (lane >> 4) * 16;

    float acc[4][2][4];
#pragma unroll
    for (int mi = 0; mi < 4; mi++)
#pragma unroll
        for (int ni = 0; ni < 2; ni++)
#pragma unroll
            for (int c = 0; c < 4; c++) acc[mi][ni][c] = 0.0f;

    // prologue
    LOAD_STAGE(0);
    asrc += 128; bsrc += 128;

    for (int kt = 0; kt < NKT; kt++) {
        cp_wait<0>();            // stage kt resident
        // Barrier orders: (a) this stage's data visible to all warps,
        // (b) all warps finished reading slot (kt+1)&1 in iter kt-1 -> safe to
        //     overwrite it below.
        __syncthreads();

        if (kt + 1 < NKT) {
            LOAD_STAGE((kt + 1) & 1);   // overlaps with compute below
            asrc += 128; bsrc += 128;
        }

        const uint32_t st = base + (kt & 1) * STAGE_BYTES;
        const uint32_t a_base = st + A_OFF + (wm + lrow) * STRIDE + lcol;
        const uint32_t b_base = st + B_OFF + (wn + lrow) * STRIDE + lcol;

#pragma unroll
        for (int ks = 0; ks < 4; ks++) {            // four k16 sub-steps
            uint32_t a[4][4];
#pragma unroll
            for (int mi = 0; mi < 4; mi++)
                ldsm4(a[mi], a_base + mi * 16 * STRIDE + ks * 32);

            uint32_t t4[4];                          // n16 x k16 -> two n8 frags
            ldsm4(t4, b_base + ks * 32);
            uint32_t b0[2] = {t4[0], t4[2]};
            uint32_t b1[2] = {t4[1], t4[3]};

#pragma unroll
            for (int mi = 0; mi < 4; mi++) {
                mma16816(acc[mi][0], a[mi], b0);
                mma16816(acc[mi][1], a[mi], b1);
            }
        }
    }

    // ---------------- epilogue: y = acc * scale + bias ----------------
    const float sc = __ldg(scale);
    const int r0 = lane >> 2;
    const int c0 = 2 * (lane & 3);

#pragma unroll
    for (int ni = 0; ni < 2; ni++) {
        const int col = gn0 + wn + ni * 8 + c0;
        const float2 bv = *reinterpret_cast<const float2*>(bias + col);
#pragma unroll
        for (int mi = 0; mi < 4; mi++) {
            const int row = gm0 + wm + mi * 16 + r0;
            float2 o0, o1;
            o0.x = acc[mi][ni][0] * sc + bv.x;
            o0.y = acc[mi][ni][1] * sc + bv.y;
            o1.x = acc[mi][ni][2] * sc + bv.x;
            o1.y = acc[mi][ni][3] * sc + bv.y;
            *reinterpret_cast<float2*>(out + (size_t)row * DOUT + col)       = o0;
            *reinterpret_cast<float2*>(out + (size_t)(row + 8) * DOUT + col) = o1;
        }
    }
}

// ---------------- launch ----------------
extern "C" void kernel_launch(void* const* d_in, const int* in_sizes, int n_in,
                              void* d_out, int out_size) {
    const float* x     = (const float*)d_in[0];
    const float* w     = (const float*)d_in[1];
    const float* bias  = (const float*)d_in[2];
    const float* scale = (const float*)d_in[3];
    float* out = (float*)d_out;

    convert_all_kernel<<<(XN4 + WN4) / 512, 512>>>((const float4*)x, (const float4*)w);

    cudaFuncSetAttribute(gemm_kernel, cudaFuncAttributeMaxDynamicSharedMemorySize, SMEM_BYTES);
    dim3 grid(DOUT / BN, TOKENS / BM);   // (64, 64)
    gemm_kernel<<<grid, NTHREADS, SMEM_BYTES>>>(bias, scale, out);
}

// round 11
// speedup vs baseline: 1.1104x; 1.0055x over previous
#include <cuda_runtime.h>
#include <cuda_fp16.h>
#include <cstdint>

// ---------------- problem constants ----------------
#define TOKENS 8192
#define DIN    4096
#define DOUT   4096

// ---------------- GEMM tiling ----------------
#define BM 128                 // CTA tile M
#define BN 64                  // CTA tile N
#define BK 64                  // fp16 elements per K stage (128B per row)
#define NKT (DIN / BK)         // 64 K iterations
#define NTHREADS 256           // 8 warps: 2 (m) x 4 (n), warp tile 64x16

// SMEM row stride: 128B data + 16B pad = 144B -> ldmatrix phases conflict-free.
#define STRIDE 144
#define A_OFF 0
#define A_BYTES (BM * STRIDE)            // 18432
#define B_OFF A_BYTES
#define B_BYTES (BN * STRIDE)            // 9216
#define STAGE_BYTES (A_BYTES + B_BYTES)  // 27648
#define SMEM_BYTES (2 * STAGE_BYTES)     // 55296 -> 3 CTAs/SM (166KB < 228KB)

// ---------------- device scratch ----------------
__device__ __half g_w[(size_t)DOUT   * DIN];   // 32 MB; codes 0..126 EXACT in fp16
__device__ __half g_x[(size_t)TOKENS * DIN];   // 64 MB; rel err <= 2^-11/element

// ---------------- PTX helpers ----------------
__device__ __forceinline__ uint32_t smem_u32(const void* p) {
    return (uint32_t)__cvta_generic_to_shared(p);
}
__device__ __forceinline__ void cp16(uint32_t s, const void* g) {
    asm volatile("cp.async.cg.shared.global [%0], [%1], 16;" :: "r"(s), "l"(g));
}
__device__ __forceinline__ void cp_commit() {
    asm volatile("cp.async.commit_group;" ::: "memory");
}
template <int N>
__device__ __forceinline__ void cp_wait() {
    asm volatile("cp.async.wait_group %0;" :: "n"(N) : "memory");
}
__device__ __forceinline__ void ldsm4(uint32_t* r, uint32_t addr) {
    asm volatile("ldmatrix.sync.aligned.m8n8.x4.shared.b16 {%0,%1,%2,%3}, [%4];"
                 : "=r"(r[0]), "=r"(r[1]), "=r"(r[2]), "=r"(r[3]) : "r"(addr));
}
__device__ __forceinline__ void mma16816(float* d, const uint32_t* a, const uint32_t* b) {
    asm volatile(
        "mma.sync.aligned.m16n8k16.row.col.f32.f16.f16.f32 "
        "{%0,%1,%2,%3}, {%4,%5,%6,%7}, {%8,%9}, {%0,%1,%2,%3};"
        : "+f"(d[0]), "+f"(d[1]), "+f"(d[2]), "+f"(d[3])
        : "r"(a[0]), "r"(a[1]), "r"(a[2]), "r"(a[3]), "r"(b[0]), "r"(b[1]));
}
// streaming loads/stores (evict-first in L2)
__device__ __forceinline__ float4 ld_cs16(const float4* p) {
    float4 v;
    asm volatile("ld.global.cs.v4.f32 {%0,%1,%2,%3}, [%4];"
                 : "=f"(v.x), "=f"(v.y), "=f"(v.z), "=f"(v.w) : "l"(p));
    return v;
}
__device__ __forceinline__ void st_cs16(void* p, uint4 v) {
    asm volatile("st.global.cs.v4.u32 [%0], {%1, %2, %3, %4};"
                 :: "l"(p), "r"(v.x), "r"(v.y), "r"(v.z), "r"(v.w));
}
__device__ __forceinline__ void st_cs8f(void* p, float2 v) {
    asm volatile("st.global.cs.v2.f32 [%0], {%1, %2};" :: "l"(p), "f"(v.x), "f"(v.y));
}

// ---------------- fused conversion kernel ----------------
// Each thread: 2 consecutive float4 reads (32B) -> one 16B fp16 store.
#define XN8 (TOKENS * DIN / 8)
#define WN8 (DOUT * DIN / 8)

__device__ __forceinline__ uint4 cvt8(float4 a, float4 b) {
    __half2 p0 = __floats2half2_rn(a.x, a.y);
    __half2 p1 = __floats2half2_rn(a.z, a.w);
    __half2 p2 = __floats2half2_rn(b.x, b.y);
    __half2 p3 = __floats2half2_rn(b.z, b.w);
    uint4 r;
    r.x = *reinterpret_cast<uint32_t*>(&p0);
    r.y = *reinterpret_cast<uint32_t*>(&p1);
    r.z = *reinterpret_cast<uint32_t*>(&p2);
    r.w = *reinterpret_cast<uint32_t*>(&p3);
    return r;
}

__global__ void convert_all_kernel(const float4* __restrict__ x,
                                   const float4* __restrict__ w) {
    int i = blockIdx.x * blockDim.x + threadIdx.x;
    if (i < XN8) {
        float4 a = ld_cs16(x + 2 * i);
        float4 b = ld_cs16(x + 2 * i + 1);
        st_cs16(reinterpret_cast<uint4*>(g_x) + i, cvt8(a, b));
    } else {
        int j = i - XN8;
        float4 a = ld_cs16(w + 2 * j);     // exact: integer codes 0..126
        float4 b = ld_cs16(w + 2 * j + 1);
        st_cs16(reinterpret_cast<uint4*>(g_w) + j, cvt8(a, b));
    }
}

// ---------------- main GEMM (round-8 optimum: 2-stage, 3 CTAs/SM) ----------------
__global__ void __launch_bounds__(NTHREADS, 3)
gemm_kernel(const float* __restrict__ bias, const float* __restrict__ scale,
            float* __restrict__ out) {
    extern __shared__ char dsm[];
    const uint32_t base = smem_u32(dsm);

    const int tid  = threadIdx.x;
    const int lane = tid & 31;
    const int wrp  = tid >> 5;                 // 8 warps: 2 (m) x 4 (n)
    const int wm   = (wrp >> 2) * 64;          // warp m offset (0/64)
    const int wn   = (wrp & 3) * 16;           // warp n offset (0/16/32/48)
    const int gn0  = blockIdx.x * BN;
    const int gm0  = blockIdx.y * BM;

    // ---- per-thread cp.async state (advance src by 128B per stage) ----
    const int lrowc = tid >> 3;
    const int lseg  = tid & 7;
    const char* asrc = (const char*)(g_x + (size_t)(gm0 + lrowc) * DIN + lseg * 8);
    const char* bsrc = (const char*)(g_w + (size_t)(gn0 + lrowc) * DIN + lseg * 8);
    const uint32_t adst = base + A_OFF + lrowc * STRIDE + lseg * 16;
    const uint32_t bdst = base + B_OFF + lrowc * STRIDE + lseg * 16;

    #define LOAD_STAGE(slot)                                                        \
        do {                                                                        \
            const uint32_t so = (slot) * STAGE_BYTES;                               \
            _Pragma("unroll")                                                       \
            for (int t = 0; t < 4; t++)                                             \
                cp16(adst + so + t * (32 * STRIDE),                                 \
                     asrc + (size_t)t * (32 * DIN * 2));                            \
            _Pragma("unroll")                                                       \
            for (int t = 0; t < 2; t++)                                             \
                cp16(bdst + so + t * (32 * STRIDE),                                 \
                     bsrc + (size_t)t * (32 * DIN * 2));                            \
            cp_commit();                                                            \
        } while (0)

    const int lrow = lane & 15;
    const int lcol = (lane >> 4) * 16;

    float acc[4][2][4];
#pragma unroll
    for (int mi = 0; mi < 4; mi++)
#pragma unroll
        for (int ni = 0; ni < 2; ni++)
#pragma unroll
            for (int c = 0; c < 4; c++) acc[mi][ni][c] = 0.0f;

    // prologue
    LOAD_STAGE(0);
    asrc += 128; bsrc += 128;

    for (int kt = 0; kt < NKT; kt++) {
        cp_wait<0>();            // stage kt resident
        // Barrier orders: (a) this stage's data visible to all warps,
        // (b) all warps finished reading slot (kt+1)&1 in iter kt-1 -> safe to
        //     overwrite it below.
        __syncthreads();

        if (kt + 1 < NKT) {
            LOAD_STAGE((kt + 1) & 1);   // overlaps with compute below
            asrc += 128; bsrc += 128;
        }

        const uint32_t st = base + (kt & 1) * STAGE_BYTES;
        const uint32_t a_base = st + A_OFF + (wm + lrow) * STRIDE + lcol;
        const uint32_t b_base = st + B_OFF + (wn + lrow) * STRIDE + lcol;

#pragma unroll
        for (int ks = 0; ks < 4; ks++) {            // four k16 sub-steps
            uint32_t a[4][4];
#pragma unroll
            for (int mi = 0; mi < 4; mi++)
                ldsm4(a[mi], a_base + mi * 16 * STRIDE + ks * 32);

            uint32_t t4[4];                          // n16 x k16 -> two n8 frags
            ldsm4(t4, b_base + ks * 32);
            uint32_t b0[2] = {t4[0], t4[2]};
            uint32_t b1[2] = {t4[1], t4[3]};

#pragma unroll
            for (int mi = 0; mi < 4; mi++) {
                mma16816(acc[mi][0], a[mi], b0);
                mma16816(acc[mi][1], a[mi], b1);
            }
        }
    }

    // ---------------- epilogue: y = acc * scale + bias (streaming stores) --------
    const float sc = __ldg(scale);
    const int r0 = lane >> 2;
    const int c0 = 2 * (lane & 3);

#pragma unroll
    for (int ni = 0; ni < 2; ni++) {
        const int col = gn0 + wn + ni * 8 + c0;
        const float2 bv = *reinterpret_cast<const float2*>(bias + col);
#pragma unroll
        for (int mi = 0; mi < 4; mi++) {
            const int row = gm0 + wm + mi * 16 + r0;
            float2 o0, o1;
            o0.x = acc[mi][ni][0] * sc + bv.x;
            o0.y = acc[mi][ni][1] * sc + bv.y;
            o1.x = acc[mi][ni][2] * sc + bv.x;
            o1.y = acc[mi][ni][3] * sc + bv.y;
            st_cs8f(out + (size_t)row * DOUT + col,       o0);
            st_cs8f(out + (size_t)(row + 8) * DOUT + col, o1);
        }
    }
}

// ---------------- launch ----------------
extern "C" void kernel_launch(void* const* d_in, const int* in_sizes, int n_in,
                              void* d_out, int out_size) {
    const float* x     = (const float*)d_in[0];
    const float* w     = (const float*)d_in[1];
    const float* bias  = (const float*)d_in[2];
    const float* scale = (const float*)d_in[3];
    float* out = (float*)d_out;

    convert_all_kernel<<<(XN8 + WN8) / 512, 512>>>((const float4*)x, (const float4*)w);

    cudaFuncSetAttribute(gemm_kernel, cudaFuncAttributeMaxDynamicSharedMemorySize, SMEM_BYTES);
    dim3 grid(DOUT / BN, TOKENS / BM);   // (64, 64)
    gemm_kernel<<<grid, NTHREADS, SMEM_BYTES>>>(bias, scale, out);
}